// round 2
// baseline (speedup 1.0000x reference)
#include <cuda_runtime.h>

// Problem shape (fixed for this registry entry)
#define B     8
#define T     200
#define U1    101        // U+1
#define V     1024
#define US    102        // padded u-stride (lane stride -101 = -5 mod 32 -> conflict-free LDS)
#define BTU   20504      // padded (T+1)*US  (blank, shifted +1 row, row0 = zeros), 16B-mult
#define LCS   20432      // padded T*US (+ overrun pad for invalid u<=127 reads), 16B-mult
#define NEGV  (-1e30f)
#define NDIAG 300        // T + U1 - 1

// Compact gathered scores, per batch (device scratch; no allocs)
__device__ __align__(16) float g_blank[B * BTU];
__device__ __align__(16) float g_lc[B * LCS];

// ---------------------------------------------------------------------------
// Kernel 1: gather the 2 useful channels out of the 662MB logits tensor.
//   g_blank physical row r stores logical blank[t=r-1]; row 0 = 0.0f so that
//   base = a_init + blank_pad reproduces the t==0 initialization with no branch.
//   g_lc[t][u] = (u==0) ? NEG : logits[b,t,u-1,labels[b,u-1]]
// Also zero-inits the scalar output (d_out is poisoned by the harness).
// ---------------------------------------------------------------------------
__global__ void gather_kernel(const float* __restrict__ logits,
                              const int* __restrict__ labels,
                              float* __restrict__ out) {
    int idx = blockIdx.x * blockDim.x + threadIdx.x;
    if (idx == 0) out[0] = 0.0f;

    // blank (row-shifted)
    if (idx < B * BTU) {
        int b = idx / BTU, li = idx % BTU;
        int r = li / US, u = li % US;
        float v = NEGV;
        if (r == 0) v = 0.0f;                               // t = -1 pad row
        else if (r <= T && u < U1)
            v = logits[((long)(b * T + (r - 1)) * U1 + u) * V];
        g_blank[idx] = v;
    }
    // label-emission cost entering column u
    if (idx < B * LCS) {
        int b = idx / LCS, li = idx % LCS;
        int t = li / US, u = li % US;
        float v = NEGV;
        if (t < T && u >= 1 && u < U1) {
            int lab = labels[b * (U1 - 1) + (u - 1)];
            v = logits[((long)(b * T + t) * U1 + (u - 1)) * V + lab];
        }
        g_lc[idx] = v;
    }
}

// ---------------------------------------------------------------------------
// Kernel 2: one CTA per batch. 256 threads stage the compact arrays into smem,
// then warp 0 alone runs the anti-diagonal wavefront with shfl-only
// communication and NO barriers in the 300-iteration loop.
//   lane L owns columns u = L, L+32, L+64, L+96 (j = 0..3)
//   alpha[t,u] = logaddexp(alpha[t-1,u] + blank[t-1,u], alpha[t,u-1] + lc[t,u])
// Column Lb freezes at t >= Tb so the answer survives in the register.
// ---------------------------------------------------------------------------
__global__ void dp_kernel(const int* __restrict__ loglen,
                          const int* __restrict__ lablen,
                          float* __restrict__ out) {
    extern __shared__ float smem[];
    float* smB = smem;          // BTU floats
    float* smL = smem + BTU;    // LCS floats

    const int b   = blockIdx.x;
    const int tid = threadIdx.x;
    const int Tb  = loglen[b];
    const int Lb  = lablen[b];

    // Stage this batch's compact arrays (coalesced float4)
    {
        const float4* sb = (const float4*)(g_blank + b * BTU);
        const float4* sl = (const float4*)(g_lc    + b * LCS);
        float4* db = (float4*)smB;
        float4* dl = (float4*)smL;
        for (int i = tid; i < BTU / 4; i += blockDim.x) db[i] = sb[i];
        for (int i = tid; i < LCS / 4; i += blockDim.x) dl[i] = sl[i];
    }
    __syncthreads();
    if (tid >= 32) return;      // DP runs on warp 0 only; no more barriers

    const int  lane  = tid;
    const int  lsrc  = (lane + 31) & 31;   // shfl source = lane-1 (wrap)
    const bool lane0 = (lane == 0);

    float a[4], bl[4], lv[4];
    int   o[4], tc[4], tlim[4];
    #pragma unroll
    for (int j = 0; j < 4; ++j) {
        int u   = lane + 32 * j;
        a[j]    = (u == 0) ? 0.0f : NEGV;   // base0 init; protected until t==0
        o[j]    = u;                        // offset for t = 0
        tc[j]   = -u;                       // t at diagonal d=0
        tlim[j] = (u == Lb) ? Tb : T;       // freeze capture column at t>=Tb
        bl[j]   = smB[o[j]];
        lv[j]   = smL[o[j]];
    }

    #pragma unroll 1
    for (int d = 0; d < NDIAG; ++d) {
        // left neighbor's previous-diagonal alpha via shfl (no smem, no bar)
        float la[4], left[4];
        #pragma unroll
        for (int j = 0; j < 4; ++j)
            la[j] = __shfl_sync(0xffffffffu, a[j], lsrc);
        left[0] = lane0 ? NEGV : la[0];
        #pragma unroll
        for (int j = 1; j < 4; ++j)
            left[j] = lane0 ? la[j - 1] : la[j];

        #pragma unroll
        for (int j = 0; j < 4; ++j) {
            float base = a[j] + bl[j];              // blank path (pad row -> t==0 init)
            float y    = left[j] + lv[j];           // label path
            float m    = fmaxf(base, y);
            float n    = fminf(base, y);
            float e    = __expf(n - m);             // EX2, underflows cleanly
            float anew = m + __logf(1.0f + e);      // LG2
            if ((unsigned)tc[j] < (unsigned)tlim[j]) a[j] = anew;  // predicated update
            if ((unsigned)tc[j] < (unsigned)(T - 1)) o[j] += US;   // predicated advance
            tc[j] += 1;
            bl[j] = smB[o[j]];                      // prefetch next diagonal
            lv[j] = smL[o[j]];
        }
    }

    // Answer = frozen register in column Lb (exactly one lane/j matches)
    #pragma unroll
    for (int j = 0; j < 4; ++j) {
        int u = lane + 32 * j;
        if (u == Lb) atomicAdd(out, -a[j] * (1.0f / B));  // mean over batch
    }
}

// ---------------------------------------------------------------------------
extern "C" void kernel_launch(void* const* d_in, const int* in_sizes, int n_in,
                              void* d_out, int out_size) {
    const float* logits = (const float*)d_in[0];
    const int*   labels = (const int*)d_in[1];
    const int*   loglen = (const int*)d_in[2];
    const int*   lablen = (const int*)d_in[3];
    float* out = (float*)d_out;

    const int total      = B * BTU;                       // covers both gathers
    const int smem_bytes = (BTU + LCS) * (int)sizeof(float);  // 163744 B

    cudaFuncSetAttribute(dp_kernel,
                         cudaFuncAttributeMaxDynamicSharedMemorySize,
                         smem_bytes);

    gather_kernel<<<(total + 255) / 256, 256>>>(logits, labels, out);
    dp_kernel<<<B, 256, smem_bytes>>>(loglen, lablen, out);
}

// round 3
// speedup vs baseline: 1.5825x; 1.5825x over previous
#include <cuda_runtime.h>
#include <cstdint>

// Problem shape (fixed for this registry entry)
#define B     8
#define T     200
#define U1    101        // U+1
#define V     1024
#define US    102        // padded u-stride (lane stride -101 = -5 mod 32 -> conflict-free LDS)
#define BTU   20504      // padded (T+1)*US (blank, shifted +1 row, row0 = zeros), 16B mult
#define LCS   20432      // padded T*US (+ overrun pad), 16B mult
#define NEGV  (-1e30f)
#define NDIAG 300        // T + U1 - 1
#define LOG2E 1.4426950408889634f
#define LN2   0.6931471805599453f

// Compact gathered scores in log2 domain, per batch (device scratch; no allocs)
__device__ __align__(16) float g_blank[B * BTU];
__device__ __align__(16) float g_lc[B * LCS];

__device__ __forceinline__ uint32_t smem_u32(const void* p) {
    uint32_t a;
    asm("{ .reg .u64 t; cvta.to.shared.u64 t, %1; cvt.u32.u64 %0, t; }"
        : "=r"(a) : "l"(p));
    return a;
}

// ---------------------------------------------------------------------------
// Kernel 1: gather the 2 useful channels out of the 662MB logits tensor,
// pre-scaled by log2(e) so the DP runs in the log2 semiring (EX2/LG2 native).
//   g_blank row r = blank[t=r-1]*LOG2E; row 0 = 0.0f (reproduces t==0 init).
//   g_lc[t][u] = (u==0) ? NEG : logits[b,t,u-1,labels[b,u-1]]*LOG2E
// Also zero-inits the scalar output.
// ---------------------------------------------------------------------------
__global__ void gather_kernel(const float* __restrict__ logits,
                              const int* __restrict__ labels,
                              float* __restrict__ out) {
    int idx = blockIdx.x * blockDim.x + threadIdx.x;
    if (idx == 0) out[0] = 0.0f;

    if (idx < B * BTU) {                               // blank (row-shifted)
        int b = idx / BTU, li = idx % BTU;
        int r = li / US, u = li % US;
        float v = NEGV;
        if (r == 0) v = 0.0f;                          // t = -1 pad row
        else if (r <= T && u < U1)
            v = logits[((long)(b * T + (r - 1)) * U1 + u) * V] * LOG2E;
        g_blank[idx] = v;
    }
    if (idx < B * LCS) {                               // label-emission cost
        int b = idx / LCS, li = idx % LCS;
        int t = li / US, u = li % US;
        float v = NEGV;
        if (t < T && u >= 1 && u < U1) {
            int lab = labels[b * (U1 - 1) + (u - 1)];
            v = logits[((long)(b * T + t) * U1 + (u - 1)) * V + lab] * LOG2E;
        }
        g_lc[idx] = v;
    }
}

// ---------------------------------------------------------------------------
// Kernel 2: one 32-thread CTA per batch (launch_bounds(32,1) -> 255-reg budget
// so ptxas can interleave the four per-lane chains). Stage compact arrays into
// smem via cp.async.bulk + mbarrier, then run the anti-diagonal wavefront with
// shfl-only communication, no barriers, in the log2 semiring.
//   lane L owns columns u = L, L+32, L+64, L+96
//   a2[t,u] = log2add(a2[t-1,u] + bl2[t-1,u], a2[t,u-1] + lc2[t,u])
// Column Lb freezes at t >= Tb; answer = frozen register * ln2.
// ---------------------------------------------------------------------------
__global__ void __launch_bounds__(32, 1)
dp_kernel(const int* __restrict__ loglen,
          const int* __restrict__ lablen,
          float* __restrict__ out) {
    extern __shared__ float smem[];
    __shared__ __align__(8) unsigned long long mbar;
    float* smB = smem;          // BTU floats
    float* smL = smem + BTU;    // LCS floats

    const int b    = blockIdx.x;
    const int lane = threadIdx.x;
    const int Tb   = loglen[b];
    const int Lb   = lablen[b];

    const uint32_t mb_a  = smem_u32(&mbar);
    const uint32_t smB_a = smem_u32(smB);
    const uint32_t smL_a = smem_u32(smL);

    if (lane == 0)
        asm volatile("mbarrier.init.shared.b64 [%0], %1;"
                     :: "r"(mb_a), "r"(1) : "memory");
    __syncwarp();
    if (lane == 0) {
        const uint32_t tx = (BTU + LCS) * 4u;
        asm volatile("mbarrier.arrive.expect_tx.shared.b64 _, [%0], %1;"
                     :: "r"(mb_a), "r"(tx) : "memory");
        asm volatile(
            "cp.async.bulk.shared::cluster.global.mbarrier::complete_tx::bytes"
            " [%0], [%1], %2, [%3];"
            :: "r"(smB_a), "l"(g_blank + b * BTU), "r"(BTU * 4u), "r"(mb_a)
            : "memory");
        asm volatile(
            "cp.async.bulk.shared::cluster.global.mbarrier::complete_tx::bytes"
            " [%0], [%1], %2, [%3];"
            :: "r"(smL_a), "l"(g_lc + b * LCS), "r"(LCS * 4u), "r"(mb_a)
            : "memory");
    }
    // All lanes wait for both bulk copies (phase parity 0)
    {
        uint32_t done = 0;
        while (!done) {
            asm volatile(
                "{\n\t.reg .pred p;\n\t"
                "mbarrier.try_wait.parity.acquire.cta.shared::cta.b64 p, [%1], %2;\n\t"
                "selp.b32 %0, 1, 0, p;\n\t}"
                : "=r"(done) : "r"(mb_a), "r"(0u) : "memory");
        }
    }

    const int  lsrc  = (lane + 31) & 31;   // shfl source = lane-1 (wrap)
    const bool lane0 = (lane == 0);

    float a[4], bl[4], lv[4];
    int   o[4], tc[4], tlim[4];
    #pragma unroll
    for (int j = 0; j < 4; ++j) {
        int u   = lane + 32 * j;
        a[j]    = (u == 0) ? 0.0f : NEGV;   // base0 init (log2 domain)
        o[j]    = u;                        // offset for t = 0
        tc[j]   = -u;                       // t at diagonal d=0
        tlim[j] = (u == Lb) ? Tb : T;       // freeze capture column at t>=Tb
        bl[j]   = smB[o[j]];
        lv[j]   = smL[o[j]];
    }

    #pragma unroll 1
    for (int d = 0; d < NDIAG; ++d) {
        float la[4], left[4];
        #pragma unroll
        for (int j = 0; j < 4; ++j)
            la[j] = __shfl_sync(0xffffffffu, a[j], lsrc);
        left[0] = lane0 ? NEGV : la[0];
        #pragma unroll
        for (int j = 1; j < 4; ++j)
            left[j] = lane0 ? la[j - 1] : la[j];

        float base[4], y[4], m[4], e[4], anew[4];
        #pragma unroll
        for (int j = 0; j < 4; ++j) {
            base[j] = a[j] + bl[j];                 // blank path
            y[j]    = left[j] + lv[j];              // label path
            m[j]    = fmaxf(base[j], y[j]);
            e[j]    = exp2f(fminf(base[j], y[j]) - m[j]);   // EX2
        }
        #pragma unroll
        for (int j = 0; j < 4; ++j) {
            anew[j] = m[j] + __log2f(1.0f + e[j]);          // LG2
            if ((unsigned)tc[j] < (unsigned)tlim[j]) a[j] = anew[j];
            if ((unsigned)tc[j] < (unsigned)(T - 1)) o[j] += US;
            tc[j] += 1;
            bl[j] = smB[o[j]];                      // prefetch next diagonal
            lv[j] = smL[o[j]];
        }
    }

    // Answer = frozen register in column Lb (exactly one lane/j matches)
    #pragma unroll
    for (int j = 0; j < 4; ++j) {
        int u = lane + 32 * j;
        if (u == Lb) atomicAdd(out, -a[j] * (LN2 / B));   // back to ln, mean
    }
}

// ---------------------------------------------------------------------------
extern "C" void kernel_launch(void* const* d_in, const int* in_sizes, int n_in,
                              void* d_out, int out_size) {
    const float* logits = (const float*)d_in[0];
    const int*   labels = (const int*)d_in[1];
    const int*   loglen = (const int*)d_in[2];
    const int*   lablen = (const int*)d_in[3];
    float* out = (float*)d_out;

    const int total      = B * BTU;
    const int smem_bytes = (BTU + LCS) * (int)sizeof(float);  // 163744 B

    cudaFuncSetAttribute(dp_kernel,
                         cudaFuncAttributeMaxDynamicSharedMemorySize,
                         smem_bytes);

    gather_kernel<<<(total + 255) / 256, 256>>>(logits, labels, out);
    dp_kernel<<<B, 32, smem_bytes>>>(loglen, lablen, out);
}

// round 5
// speedup vs baseline: 2.5324x; 1.6003x over previous
#include <cuda_runtime.h>
#include <cuda_bf16.h>
#include <cstdint>

// Problem shape (fixed for this registry entry)
#define B     8
#define T     200
#define U1    101        // U+1
#define V     1024
#define UD    104        // padded u-stride in diagonal-major layout (26 x 16B rows)
#define ND    300        // number of diagonals (T + U1 - 1)
#define LN2   0.6931471805599453f

// Diagonal-major packed scores: g_sc[b][d][u] = bf16x2( Bl, Lc ) where
//   Bl = exp(blank[t-1,u])  (neutral 1.0 if t<1 or cell invalid)
//   Lc = exp(lab  [t,  u])  (neutral 0.0 if u<1 or cell invalid),  t = d-u
__device__ __align__(16) __nv_bfloat162 g_sc[B * ND * UD];

__device__ __forceinline__ uint32_t smem_u32(const void* p) {
    uint32_t a;
    asm("{ .reg .u64 t; cvta.to.shared.u64 t, %1; cvt.u32.u64 %0, t; }"
        : "=r"(a) : "l"(p));
    return a;
}

// ---------------------------------------------------------------------------
// Kernel 1: gather + exponentiate the 2 useful channels of the 662MB logits
// tensor into a diagonal-major bf16x2 table with neutral pads, so the DP loop
// has zero branches. Also zero-inits the scalar output.
// ---------------------------------------------------------------------------
__global__ void gather_kernel(const float* __restrict__ logits,
                              const int* __restrict__ labels,
                              float* __restrict__ out) {
    int idx = blockIdx.x * blockDim.x + threadIdx.x;
    if (idx == 0) out[0] = 0.0f;
    if (idx >= B * ND * UD) return;

    int u = idx % UD;
    int d = (idx / UD) % ND;
    int b = idx / (UD * ND);
    int t = d - u;

    float bl = 1.0f, lc = 0.0f;                    // neutral: a' = a*1 + left*0
    if (u < U1 && t >= 0 && t < T) {
        if (t >= 1)
            bl = __expf(logits[((long)(b * T + (t - 1)) * U1 + u) * V]);
        if (u >= 1) {
            int lab = labels[b * (U1 - 1) + (u - 1)];
            lc = __expf(logits[((long)(b * T + t) * U1 + (u - 1)) * V + lab]);
        }
    }
    g_sc[idx] = __floats2bfloat162_rn(bl, lc);
}

// ---------------------------------------------------------------------------
// Kernel 2: one 32-thread CTA per batch. Bulk-copy the 125KB diagonal table
// into smem, then run the wavefront in LINEAR (probability) domain:
//   A[t,u] = A[t-1,u]*Bl + A[t,u-1]*Lc      (chain = 1 FFMA per diagonal)
// lane L owns u = 4L..4L+3 (contiguous): lefts are registers, 1 shfl/diag.
// Power-of-2 renorm every 8 diagonals (exact), exponent tracked in S.
// Stop at capD = Tb-1+Lb; answer = a[Lb&3] on lane Lb>>2.
// ---------------------------------------------------------------------------
__global__ void __launch_bounds__(32, 1)
dp_kernel(const int* __restrict__ loglen,
          const int* __restrict__ lablen,
          float* __restrict__ out) {
    extern __shared__ __align__(16) uint4 sm[];   // (ND+1) rows x UD cells x 4B
    __shared__ __align__(8) unsigned long long mbar;

    const int b    = blockIdx.x;
    const int lane = threadIdx.x;

    const uint32_t mb_a = smem_u32(&mbar);
    const uint32_t sm_a = smem_u32(sm);

    if (lane == 0)
        asm volatile("mbarrier.init.shared.b64 [%0], %1;"
                     :: "r"(mb_a), "r"(1) : "memory");
    __syncwarp();
    if (lane == 0) {
        const uint32_t tx = ND * UD * 4u;          // 124800 bytes
        asm volatile("mbarrier.arrive.expect_tx.shared.b64 _, [%0], %1;"
                     :: "r"(mb_a), "r"(tx) : "memory");
        asm volatile(
            "cp.async.bulk.shared::cluster.global.mbarrier::complete_tx::bytes"
            " [%0], [%1], %2, [%3];"
            :: "r"(sm_a), "l"(g_sc + b * ND * UD), "r"(tx), "r"(mb_a)
            : "memory");
    }
    {   // wait phase 0
        uint32_t done = 0;
        while (!done) {
            asm volatile(
                "{\n\t.reg .pred p;\n\t"
                "mbarrier.try_wait.parity.acquire.cta.shared::cta.b64 p, [%1], %2;\n\t"
                "selp.b32 %0, 1, 0, p;\n\t}"
                : "=r"(done) : "r"(mb_a), "r"(0u) : "memory");
        }
    }

    const int Tb   = loglen[b];
    const int Lb   = lablen[b];
    const int capD = Tb - 1 + Lb;                  // last diagonal we need

    float a0 = (lane == 0) ? 1.0f : 0.0f;          // A[.,u=0] seed (exp(0)=1)
    float a1 = 0.0f, a2 = 0.0f, a3 = 0.0f;
    int   S  = 0;                                  // accumulated exponent

    // Per-lane row pointer: row d at sm + d*(UD/4), lane slice = lane (16B)
    const uint4* p  = sm + lane;                   // 16B per lane per row
    uint4 cur = p[0];

    #pragma unroll 1
    for (int d = 0; d <= capD; ++d) {
        if ((d & 7) == 0) {                        // exact power-of-2 renorm
            float mx = fmaxf(fmaxf(a0, a1), fmaxf(a2, a3));
            #pragma unroll
            for (int off = 16; off > 0; off >>= 1)
                mx = fmaxf(mx, __shfl_xor_sync(0xffffffffu, mx, off));
            int e = (__float_as_int(mx) >> 23) - 127;
            float s = __int_as_float((127 - e) << 23);   // 2^-e, exact
            a0 *= s; a1 *= s; a2 *= s; a3 *= s;
            S += e;
        }
        float l0 = __shfl_sync(0xffffffffu, a3, (lane + 31) & 31); // prev-diag a3 of lane-1
        uint4 nxt = p[(d + 1) * (UD / 4)];         // prefetch next diagonal

        const __nv_bfloat162* c = (const __nv_bfloat162*)&cur;
        float2 f0 = __bfloat1622float2(c[0]);
        float2 f1 = __bfloat1622float2(c[1]);
        float2 f2 = __bfloat1622float2(c[2]);
        float2 f3 = __bfloat1622float2(c[3]);

        float o0 = a0, o1 = a1, o2 = a2;           // lefts (prev-diag values)
        a0 = fmaf(a0, f0.x, l0 * f0.y);
        a1 = fmaf(a1, f1.x, o0 * f1.y);
        a2 = fmaf(a2, f2.x, o1 * f2.y);
        a3 = fmaf(a3, f3.x, o2 * f3.y);
        cur = nxt;
    }

    if (lane == (Lb >> 2)) {
        int ck = Lb & 3;
        float cap = (ck == 0) ? a0 : (ck == 1) ? a1 : (ck == 2) ? a2 : a3;
        float loss = -(log2f(cap) + (float)S) * LN2;   // back to nats
        atomicAdd(out, loss * (1.0f / B));             // mean over batch
    }
}

// ---------------------------------------------------------------------------
extern "C" void kernel_launch(void* const* d_in, const int* in_sizes, int n_in,
                              void* d_out, int out_size) {
    const float* logits = (const float*)d_in[0];
    const int*   labels = (const int*)d_in[1];
    const int*   loglen = (const int*)d_in[2];
    const int*   lablen = (const int*)d_in[3];
    float* out = (float*)d_out;

    const int total      = B * ND * UD;                       // 249600
    const int smem_bytes = (ND + 1) * UD * 4;                 // 125216 B

    cudaFuncSetAttribute(dp_kernel,
                         cudaFuncAttributeMaxDynamicSharedMemorySize,
                         smem_bytes);

    gather_kernel<<<(total + 255) / 256, 256>>>(logits, labels, out);
    dp_kernel<<<B, 32, smem_bytes>>>(loglen, lablen, out);
}

// round 6
// speedup vs baseline: 3.6263x; 1.4320x over previous
#include <cuda_runtime.h>
#include <cuda_bf16.h>
#include <cstdint>

// Problem shape (fixed for this registry entry)
#define B     8
#define T     200
#define U1    101        // U+1
#define V     1024
#define UD    104        // padded u-stride in diagonal-major layout (26 x 16B rows)
#define ND    300        // number of diagonals (T + U1 - 1)
#define LN2   0.6931471805599453f

// Diagonal-major packed scores: g_sc[b][d][u] = bf16x2( Bl, Lc ) where
//   Bl = exp(blank[t-1,u])  (neutral 1.0 if t<1 or cell invalid)
//   Lc = exp(lab  [t,  u])  (neutral 0.0 if u<1 or cell invalid),  t = d-u
__device__ __align__(16) __nv_bfloat162 g_sc[B * ND * UD];

__device__ __forceinline__ uint32_t smem_u32(const void* p) {
    uint32_t a;
    asm("{ .reg .u64 t; cvta.to.shared.u64 t, %1; cvt.u32.u64 %0, t; }"
        : "=r"(a) : "l"(p));
    return a;
}

// ---------------------------------------------------------------------------
// Kernel 1: gather + exponentiate the 2 useful channels of the 662MB logits
// tensor into a diagonal-major bf16x2 table with neutral pads (branch-free DP).
// Also zero-inits the scalar output.
// ---------------------------------------------------------------------------
__global__ void gather_kernel(const float* __restrict__ logits,
                              const int* __restrict__ labels,
                              float* __restrict__ out) {
    int idx = blockIdx.x * blockDim.x + threadIdx.x;
    if (idx == 0) out[0] = 0.0f;
    if (idx >= B * ND * UD) return;

    int u = idx % UD;
    int d = (idx / UD) % ND;
    int b = idx / (UD * ND);
    int t = d - u;

    float bl = 1.0f, lc = 0.0f;                    // neutral: a' = a*1 + left*0
    if (u < U1 && t >= 0 && t < T) {
        if (t >= 1)
            bl = __expf(logits[((long)(b * T + (t - 1)) * U1 + u) * V]);
        if (u >= 1) {
            int lab = labels[b * (U1 - 1) + (u - 1)];
            lc = __expf(logits[((long)(b * T + t) * U1 + (u - 1)) * V + lab]);
        }
    }
    g_sc[idx] = __floats2bfloat162_rn(bl, lc);
}

// ---------------------------------------------------------------------------
// Kernel 2: one 32-thread CTA per batch. Bulk-copy the 125KB diagonal table
// into smem, then run the wavefront in LINEAR (probability) domain:
//   A[t,u] = A[t-1,u]*Bl + A[t,u-1]*Lc
// lane L owns u = 4L..4L+3 (contiguous): lefts are registers, 1 shfl/diag.
// Diagonals processed in 16-blocks, inner loop FULLY UNROLLED (immediate LDS
// offsets, deep pipelining window); exact power-of-2 renorm at block starts.
// ---------------------------------------------------------------------------
struct DPState { float a0, a1, a2, a3; };

__device__ __forceinline__ void dp_step(DPState& s, const uint4* p, int k,
                                        int lsrc) {
    uint4 cur = p[k * (UD / 4)];                       // immediate LDS offset
    float l0  = __shfl_sync(0xffffffffu, s.a3, lsrc);  // lane-1 prev-diag a3
    const __nv_bfloat162* c = (const __nv_bfloat162*)&cur;
    float2 f0 = __bfloat1622float2(c[0]);
    float2 f1 = __bfloat1622float2(c[1]);
    float2 f2 = __bfloat1622float2(c[2]);
    float2 f3 = __bfloat1622float2(c[3]);
    float o0 = s.a0, o1 = s.a1, o2 = s.a2;             // prev-diagonal lefts
    s.a0 = fmaf(s.a0, f0.x, l0 * f0.y);
    s.a1 = fmaf(s.a1, f1.x, o0 * f1.y);
    s.a2 = fmaf(s.a2, f2.x, o1 * f2.y);
    s.a3 = fmaf(s.a3, f3.x, o2 * f3.y);
}

__device__ __forceinline__ void renorm(DPState& s, int& S) {
    float mx = fmaxf(fmaxf(s.a0, s.a1), fmaxf(s.a2, s.a3));
    #pragma unroll
    for (int off = 16; off > 0; off >>= 1)
        mx = fmaxf(mx, __shfl_xor_sync(0xffffffffu, mx, off));
    int e = (__float_as_int(mx) >> 23) - 127;
    float sc = __int_as_float((127 - e) << 23);        // 2^-e, exact
    s.a0 *= sc; s.a1 *= sc; s.a2 *= sc; s.a3 *= sc;
    S += e;
}

__global__ void __launch_bounds__(32, 1)
dp_kernel(const int* __restrict__ loglen,
          const int* __restrict__ lablen,
          float* __restrict__ out) {
    extern __shared__ __align__(16) uint4 sm[];        // ND rows x UD cells x 4B
    __shared__ __align__(8) unsigned long long mbar;

    const int b    = blockIdx.x;
    const int lane = threadIdx.x;

    const uint32_t mb_a = smem_u32(&mbar);
    const uint32_t sm_a = smem_u32(sm);

    if (lane == 0)
        asm volatile("mbarrier.init.shared.b64 [%0], %1;"
                     :: "r"(mb_a), "r"(1) : "memory");
    __syncwarp();
    if (lane == 0) {
        const uint32_t tx = ND * UD * 4u;              // 124800 bytes
        asm volatile("mbarrier.arrive.expect_tx.shared.b64 _, [%0], %1;"
                     :: "r"(mb_a), "r"(tx) : "memory");
        asm volatile(
            "cp.async.bulk.shared::cluster.global.mbarrier::complete_tx::bytes"
            " [%0], [%1], %2, [%3];"
            :: "r"(sm_a), "l"(g_sc + b * ND * UD), "r"(tx), "r"(mb_a)
            : "memory");
    }
    {   // wait phase 0
        uint32_t done = 0;
        while (!done) {
            asm volatile(
                "{\n\t.reg .pred p;\n\t"
                "mbarrier.try_wait.parity.acquire.cta.shared::cta.b64 p, [%1], %2;\n\t"
                "selp.b32 %0, 1, 0, p;\n\t}"
                : "=r"(done) : "r"(mb_a), "r"(0u) : "memory");
        }
    }

    const int Tb     = loglen[b];
    const int Lb     = lablen[b];
    const int nSteps = Tb + Lb;                        // diags 0..capD inclusive
    const int nBlk   = nSteps >> 4;
    const int rem    = nSteps & 15;

    DPState s;
    s.a0 = (lane == 0) ? 1.0f : 0.0f;                  // A[.,u=0] seed (exp(0)=1)
    s.a1 = 0.0f; s.a2 = 0.0f; s.a3 = 0.0f;
    int S = 0;

    const int   lsrc = (lane + 31) & 31;
    const uint4* p   = sm + lane;                      // 16B per lane per row

    #pragma unroll 1
    for (int blk = 0; blk < nBlk; ++blk) {
        renorm(s, S);
        #pragma unroll
        for (int k = 0; k < 16; ++k)
            dp_step(s, p, k, lsrc);
        p += 16 * (UD / 4);
    }
    if (rem) {
        renorm(s, S);
        #pragma unroll 1
        for (int k = 0; k < rem; ++k)
            dp_step(s, p, k, lsrc);
    }

    if (lane == (Lb >> 2)) {
        int ck = Lb & 3;
        float cap = (ck == 0) ? s.a0 : (ck == 1) ? s.a1
                  : (ck == 2) ? s.a2 : s.a3;
        float loss = -(log2f(cap) + (float)S) * LN2;   // back to nats
        atomicAdd(out, loss * (1.0f / B));             // mean over batch
    }
}

// ---------------------------------------------------------------------------
extern "C" void kernel_launch(void* const* d_in, const int* in_sizes, int n_in,
                              void* d_out, int out_size) {
    const float* logits = (const float*)d_in[0];
    const int*   labels = (const int*)d_in[1];
    const int*   loglen = (const int*)d_in[2];
    const int*   lablen = (const int*)d_in[3];
    float* out = (float*)d_out;

    const int total      = B * ND * UD;                // 249600
    const int smem_bytes = ND * UD * 4;                // 124800 B

    cudaFuncSetAttribute(dp_kernel,
                         cudaFuncAttributeMaxDynamicSharedMemorySize,
                         smem_bytes);

    gather_kernel<<<(total + 255) / 256, 256>>>(logits, labels, out);
    dp_kernel<<<B, 32, smem_bytes>>>(loglen, lablen, out);
}